// round 1
// baseline (speedup 1.0000x reference)
#include <cuda_runtime.h>
#include <cuda_bf16.h>
#include <math.h>

#define IH 1024
#define IW 1024
#define NB 8
#define NC 3
#define TILE 32

// shared tile widths (row-padded)
// s_img: 38x38 used (halo 3), s_gm: 36x36 (halo 2), s_t/s_q: 34x34 (halo 1)

__global__ __launch_bounds__(256)
void canny_fused_kernel(const float* __restrict__ img, float* __restrict__ out)
{
    __shared__ float s_img[38][40];
    __shared__ float s_gm [36][40];
    __shared__ float s_t  [34][36];
    __shared__ float s_q  [34][36];

    const int b  = blockIdx.z;
    const int x0 = blockIdx.x * TILE;
    const int y0 = blockIdx.y * TILE;
    const int tid = threadIdx.y * 32 + threadIdx.x;

    const float* imgb = img + (size_t)b * NC * IH * IW;

    // ---- Phase 1: load channel-summed image, halo 3 (zeros outside image) ----
    for (int idx = tid; idx < 38 * 38; idx += 256) {
        int r = idx / 38, c = idx % 38;
        int gy = y0 - 3 + r, gx = x0 - 3 + c;
        float v = 0.0f;
        if (gy >= 0 && gy < IH && gx >= 0 && gx < IW) {
            size_t o = (size_t)gy * IW + gx;
            v = imgb[o] + imgb[o + (size_t)IH * IW] + imgb[o + 2 * (size_t)IH * IW];
        }
        s_img[r][c] = v;
    }
    __syncthreads();

    // ---- Phase 2: gradient magnitude, halo 2 (0 outside image = conv padding) ----
    for (int idx = tid; idx < 36 * 36; idx += 256) {
        int r = idx / 36, c = idx % 36;
        int gy = y0 - 2 + r, gx = x0 - 2 + c;
        float m = 0.0f;
        if (gy >= 0 && gy < IH && gx >= 0 && gx < IW) {
            float a00 = s_img[r][c],     a01 = s_img[r][c+1],   a02 = s_img[r][c+2];
            float a10 = s_img[r+1][c],                          a12 = s_img[r+1][c+2];
            float a20 = s_img[r+2][c],   a21 = s_img[r+2][c+1], a22 = s_img[r+2][c+2];
            float sx = (0.5f*(a02 - a00) + (a12 - a10) + 0.5f*(a22 - a20)) / 3.0f;
            float sy = (0.5f*(a20 - a00) + (a21 - a01) + 0.5f*(a22 - a02)) / 3.0f;
            m = sqrtf(sx * sx + sy * sy);
        }
        s_gm[r][c] = m;
    }
    __syncthreads();

    // ---- Phase 3: NMS -> t in {0, 0.5, 1.0} and rounded orientation q, halo 1 ----
    for (int idx = tid; idx < 34 * 34; idx += 256) {
        int r = idx / 34, c = idx % 34;
        int gy = y0 - 1 + r, gx = x0 - 1 + c;
        float t = 0.0f, q = 0.0f;
        if (gy >= 0 && gy < IH && gx >= 0 && gx < IW) {
            float a00 = s_img[r+1][c+1], a01 = s_img[r+1][c+2], a02 = s_img[r+1][c+3];
            float a10 = s_img[r+2][c+1],                        a12 = s_img[r+2][c+3];
            float a20 = s_img[r+3][c+1], a21 = s_img[r+3][c+2], a22 = s_img[r+3][c+3];
            float sx = (0.5f*(a02 - a00) + (a12 - a10) + 0.5f*(a22 - a20)) / 3.0f;
            float sy = (0.5f*(a20 - a00) + (a21 - a01) + 0.5f*(a22 - a02)) / 3.0f;

            // orientation: atan (NOT atan2), *360/pi + 180, round-half-even(/45)
            float orient = atanf(sy / sx) * 114.59155902616465f + 180.0f;
            q = rintf(orient / 45.0f);           // in [0,8], or NaN

            float gmc  = s_gm[r+1][c+1];
            float thin = gmc;
            if (q == q) {                        // not NaN -> exactly one oriented pair
                int k = ((int)q) & 3;            // (q%8)%4
                // offs[k] = (dy,dx): (0,1) (-1,1) (-1,0) (-1,-1); neg = -off
                const int DY[4] = {0, -1, -1, -1};
                const int DX[4] = {1,  1,  0, -1};
                float dp = gmc - s_gm[r+1 + DY[k]][c+1 + DX[k]];
                float dn = gmc - s_gm[r+1 - DY[k]][c+1 - DX[k]];
                if (!(fminf(dp, dn) > 0.0f)) thin = 0.0f;   // not a local max -> remove
            }
            t = (thin > 0.5f ? 0.5f : 0.0f) + (thin > 1.0f ? 0.5f : 0.0f);
        }
        s_t[r][c] = t;
        s_q[r][c] = q;
    }
    __syncthreads();

    // ---- Phase 4: hysteresis + write all 5 output planes (32x32 center) ----
    const size_t plane = (size_t)NB * IH * IW;
    float* o_gx = out;
    float* o_gy = out + plane;
    float* o_gm = out + 2 * plane;
    float* o_or = out + 3 * plane;
    float* o_te = out + 4 * plane;

    #pragma unroll
    for (int k = 0; k < 4; k++) {
        int iy = threadIdx.y + k * 8;   // 0..31
        int ix = threadIdx.x;           // 0..31
        int gy = y0 + iy, gx = x0 + ix;

        // recompute gx/gy for output (taps: s_img rows iy+2..iy+4, cols ix+2..ix+4)
        float a00 = s_img[iy+2][ix+2], a01 = s_img[iy+2][ix+3], a02 = s_img[iy+2][ix+4];
        float a10 = s_img[iy+3][ix+2],                          a12 = s_img[iy+3][ix+4];
        float a20 = s_img[iy+4][ix+2], a21 = s_img[iy+4][ix+3], a22 = s_img[iy+4][ix+4];
        float sx = (0.5f*(a02 - a00) + (a12 - a10) + 0.5f*(a22 - a20)) / 3.0f;
        float sy = (0.5f*(a20 - a00) + (a21 - a01) + 0.5f*(a22 - a02)) / 3.0f;

        float gm = s_gm[iy+2][ix+2];
        float q  = s_q [iy+1][ix+1];
        float tc = s_t [iy+1][ix+1];

        float sum = s_t[iy  ][ix] + s_t[iy  ][ix+1] + s_t[iy  ][ix+2]
                  + s_t[iy+1][ix] + tc              + s_t[iy+1][ix+2]
                  + s_t[iy+2][ix] + s_t[iy+2][ix+1] + s_t[iy+2][ix+2];

        float high    = (tc == 1.0f) ? 1.0f : 0.0f;
        float weak_hi = ((sum * 1.25f > 1.0f) && (tc == 0.5f)) ? 1.0f : 0.0f;

        size_t o = (size_t)b * IH * IW + (size_t)gy * IW + gx;
        o_gx[o] = sx;
        o_gy[o] = sy;
        o_gm[o] = gm;
        o_or[o] = q * 45.0f;
        o_te[o] = high + weak_hi;
    }
}

extern "C" void kernel_launch(void* const* d_in, const int* in_sizes, int n_in,
                              void* d_out, int out_size)
{
    const float* img = (const float*)d_in[0];
    float* out = (float*)d_out;
    dim3 block(32, 8, 1);
    dim3 grid(IW / TILE, IH / TILE, NB);
    canny_fused_kernel<<<grid, block>>>(img, out);
}

// round 2
// speedup vs baseline: 1.1943x; 1.1943x over previous
#include <cuda_runtime.h>
#include <cuda_bf16.h>
#include <math.h>

#define IH 1024
#define IW 1024
#define NB 8
#define NC 3
#define TILE 32

// tan((2k+1)*pi/16), k=0..3
#define T0 0.1989123673796580f
#define T1 0.6681786379192989f
#define T2 1.4966057626654890f
#define T3 5.0273394921258481f

// Sobel (cross-correlation, reference kernel [[-.5,0,.5],[-1,0,1],[-.5,0,.5]]) / 3
__device__ __forceinline__ void sobel3(const float (*__restrict__ s)[40], int r, int c,
                                       float& sx, float& sy)
{
    float a00 = s[r][c],   a01 = s[r][c+1],   a02 = s[r][c+2];
    float a10 = s[r+1][c],                    a12 = s[r+1][c+2];
    float a20 = s[r+2][c], a21 = s[r+2][c+1], a22 = s[r+2][c+2];
    sx = (0.5f*(a02 - a00) + (a12 - a10) + 0.5f*(a22 - a20)) * (1.0f/3.0f);
    sy = (0.5f*(a20 - a00) + (a21 - a01) + 0.5f*(a22 - a02)) * (1.0f/3.0f);
}

template<bool EDGE>
__device__ __forceinline__ void canny_body(
    const float* __restrict__ imgb, float* __restrict__ out,
    int b, int x0, int y0, int tx, int ty,
    float (*__restrict__ s_img)[40],
    float (*__restrict__ s_sx)[40], float (*__restrict__ s_sy)[40],
    float (*__restrict__ s_gm)[40],
    float (*__restrict__ s_t)[36],  float (*__restrict__ s_q)[36])
{
    // ---- Phase 1: channel-summed image, halo 3 ----
    #pragma unroll
    for (int r = ty; r < 38; r += 8) {
        int gy = y0 - 3 + r;
        {
            int c = tx, gx = x0 - 3 + c;
            float v = 0.0f;
            if (!EDGE || (gy >= 0 && gy < IH && gx >= 0 && gx < IW)) {
                size_t o = (size_t)gy * IW + gx;
                v = imgb[o] + imgb[o + (size_t)IH*IW] + imgb[o + 2*(size_t)IH*IW];
            }
            s_img[r][c] = v;
        }
        if (tx < 6) {
            int c = tx + 32, gx = x0 - 3 + c;
            float v = 0.0f;
            if (!EDGE || (gy >= 0 && gy < IH && gx >= 0 && gx < IW)) {
                size_t o = (size_t)gy * IW + gx;
                v = imgb[o] + imgb[o + (size_t)IH*IW] + imgb[o + 2*(size_t)IH*IW];
            }
            s_img[r][c] = v;
        }
    }
    __syncthreads();

    // ---- Phase 2: sobel once -> sx, sy, gm (halo 2; zero outside image) ----
    #pragma unroll
    for (int r = ty; r < 36; r += 8) {
        int gy = y0 - 2 + r;
        #pragma unroll
        for (int cc = 0; cc < 2; cc++) {
            int c = tx + cc * 32;
            if (cc == 1 && tx >= 4) break;
            float sx = 0.0f, sy = 0.0f, m = 0.0f;
            int gx = x0 - 2 + c;
            if (!EDGE || (gy >= 0 && gy < IH && gx >= 0 && gx < IW)) {
                sobel3(s_img, r, c, sx, sy);
                m = sqrtf(sx * sx + sy * sy);
            }
            s_sx[r][c] = sx; s_sy[r][c] = sy; s_gm[r][c] = m;
        }
    }
    __syncthreads();

    // ---- Phase 3: orientation quantization + NMS -> t, q (halo 1) ----
    #pragma unroll
    for (int r = ty; r < 34; r += 8) {
        int gy = y0 - 1 + r;
        #pragma unroll
        for (int cc = 0; cc < 2; cc++) {
            int c = tx + cc * 32;
            if (cc == 1 && tx >= 2) break;
            float t = 0.0f, qv = 0.0f;
            int gx = x0 - 1 + c;
            if (!EDGE || (gy >= 0 && gy < IH && gx >= 0 && gx < IW)) {
                float sx  = s_sx[r+1][c+1];
                float sy  = s_sy[r+1][c+1];
                float gmc = s_gm[r+1][c+1];
                float ax = fabsf(sx), ay = fabsf(sy);
                // m = #thresholds crossed by |sy/sx|; q = 4 + sign(sy/sx)*m
                int m = (int)(ay > T0*ax) + (int)(ay > T1*ax)
                      + (int)(ay > T2*ax) + (int)(ay > T3*ax);
                int neg = (__float_as_int(sx) ^ __float_as_int(sy)) < 0;
                int q = neg ? (4 - m) : (4 + m);
                // orientation NaN only when sx==sy==0 (atan(0/0))
                qv = (ax == 0.0f && ay == 0.0f) ? __int_as_float(0x7fc00000) : (float)q;

                int k = q & 3;              // oriented pair index
                int dy = (k == 0) ? 0 : -1; // offs: (0,1)(-1,1)(-1,0)(-1,-1)
                int dx = 1 - (int)(k >= 2) - (int)(k == 3);
                float dp = gmc - s_gm[r+1 + dy][c+1 + dx];
                float dn = gmc - s_gm[r+1 - dy][c+1 - dx];
                float thin = (fminf(dp, dn) > 0.0f) ? gmc : 0.0f;
                t = (thin > 0.5f ? 0.5f : 0.0f) + (thin > 1.0f ? 0.5f : 0.0f);
            }
            s_t[r][c] = t;
            s_q[r][c] = qv;
        }
    }
    __syncthreads();

    // ---- Phase 4: hysteresis + write 5 planes (32x32 center) ----
    const size_t plane = (size_t)NB * IH * IW;
    float* o_gx = out;
    float* o_gy = out + plane;
    float* o_gm = out + 2 * plane;
    float* o_or = out + 3 * plane;
    float* o_te = out + 4 * plane;

    #pragma unroll
    for (int k = 0; k < 4; k++) {
        int iy = ty + k * 8;
        int ix = tx;
        float sx = s_sx[iy+2][ix+2];
        float sy = s_sy[iy+2][ix+2];
        float gm = s_gm[iy+2][ix+2];
        float qv = s_q [iy+1][ix+1];
        float tc = s_t [iy+1][ix+1];

        float sum = s_t[iy  ][ix] + s_t[iy  ][ix+1] + s_t[iy  ][ix+2]
                  + s_t[iy+1][ix] + tc              + s_t[iy+1][ix+2]
                  + s_t[iy+2][ix] + s_t[iy+2][ix+1] + s_t[iy+2][ix+2];

        float high    = (tc == 1.0f) ? 1.0f : 0.0f;
        float weak_hi = ((sum * 1.25f > 1.0f) && (tc == 0.5f)) ? 1.0f : 0.0f;

        size_t o = (size_t)b * IH * IW + (size_t)(y0 + iy) * IW + (x0 + ix);
        o_gx[o] = sx;
        o_gy[o] = sy;
        o_gm[o] = gm;
        o_or[o] = qv * 45.0f;
        o_te[o] = high + weak_hi;
    }
}

__global__ __launch_bounds__(256)
void canny_fused_kernel(const float* __restrict__ img, float* __restrict__ out)
{
    __shared__ float s_img[38][40];
    __shared__ float s_sx [36][40];
    __shared__ float s_sy [36][40];
    __shared__ float s_gm [36][40];
    __shared__ float s_t  [34][36];
    __shared__ float s_q  [34][36];

    const int b  = blockIdx.z;
    const int x0 = blockIdx.x * TILE;
    const int y0 = blockIdx.y * TILE;
    const int tx = threadIdx.x;
    const int ty = threadIdx.y;

    const float* imgb = img + (size_t)b * NC * IH * IW;

    const bool edge = (x0 == 0) || (y0 == 0) || (x0 + TILE == IW) || (y0 + TILE == IH);
    if (edge)
        canny_body<true >(imgb, out, b, x0, y0, tx, ty, s_img, s_sx, s_sy, s_gm, s_t, s_q);
    else
        canny_body<false>(imgb, out, b, x0, y0, tx, ty, s_img, s_sx, s_sy, s_gm, s_t, s_q);
}

extern "C" void kernel_launch(void* const* d_in, const int* in_sizes, int n_in,
                              void* d_out, int out_size)
{
    const float* img = (const float*)d_in[0];
    float* out = (float*)d_out;
    dim3 block(32, 8, 1);
    dim3 grid(IW / TILE, IH / TILE, NB);
    canny_fused_kernel<<<grid, block>>>(img, out);
}

// round 3
// speedup vs baseline: 1.3776x; 1.1534x over previous
#include <cuda_runtime.h>
#include <cuda_bf16.h>
#include <math.h>

#define IH 1024
#define IW 1024
#define NB 8
#define TW 32
#define TH 64

// tan((2k+1)*pi/16)
#define T0 0.1989123673796580f
#define T1 0.6681786379192989f
#define T2 1.4966057626654890f
#define T3 5.0273394921258481f
#define INV3 0.3333333333333333f

// SMEM: buf0 (72x40) holds s_img for P1/P2, then s_t (66x36) for P3/P4.
// s_sx/s_sy/s_gm: 68x40. Total 44160 B static.

template<bool EDGE>
__device__ __forceinline__ void body(
    const float* __restrict__ imgb, float* __restrict__ out,
    int b, int x0, int y0, int tx, int ty, int tid,
    float* __restrict__ buf0,
    float (*__restrict__ s_sx)[40], float (*__restrict__ s_sy)[40],
    float (*__restrict__ s_gm)[40])
{
    float (*__restrict__ s_img)[40] = (float (*)[40])buf0;

    // ---- P1: channel-summed image, rows 0..69, cols 0..37 (halo 3) ----
    #pragma unroll
    for (int m = 0; m < 9; m++) {
        int r = ty + 8 * m;
        if (r < 70) {
            int gy = y0 - 3 + r, gx = x0 - 3 + tx;
            float v = 0.0f;
            if (!EDGE || ((unsigned)gy < IH && (unsigned)gx < IW)) {
                size_t o = (size_t)gy * IW + gx;
                v = imgb[o] + imgb[o + IH * IW] + imgb[o + 2 * IH * IW];
            }
            s_img[r][tx] = v;
        }
    }
    #pragma unroll
    for (int p = 0; p < 2; p++) {                 // extra cols 32..37
        int idx = tid + 256 * p;
        if (idx < 420) {
            int r = idx / 6, c = 32 + idx % 6;
            int gy = y0 - 3 + r, gx = x0 - 3 + c;
            float v = 0.0f;
            if (!EDGE || ((unsigned)gy < IH && (unsigned)gx < IW)) {
                size_t o = (size_t)gy * IW + gx;
                v = imgb[o] + imgb[o + IH * IW] + imgb[o + 2 * IH * IW];
            }
            s_img[r][c] = v;
        }
    }
    __syncthreads();

    // ---- P2: separable sobel w/ vertical register rolling. rows 0..67, cols 0..35 ----
    {
        int base = (68 * ty) >> 3;
        int cnt  = ((68 * (ty + 1)) >> 3) - base;
        int c = tx;
        float a0 = s_img[base][c], a1 = s_img[base][c + 1], a2 = s_img[base][c + 2];
        float u0 = a2 - a0, v0 = 0.5f * (a0 + a2) + a1;
        float b0 = s_img[base + 1][c], b1 = s_img[base + 1][c + 1], b2 = s_img[base + 1][c + 2];
        float u1 = b2 - b0, v1 = 0.5f * (b0 + b2) + b1;
        #pragma unroll
        for (int j = 0; j < 9; j++) {
            int r = base + j;
            float c0 = s_img[r + 2][c], c1 = s_img[r + 2][c + 1], c2 = s_img[r + 2][c + 2];
            float u2 = c2 - c0, v2 = 0.5f * (c0 + c2) + c1;
            float sx = (0.5f * (u0 + u2) + u1) * INV3;
            float sy = (v2 - v0) * INV3;
            float gm = sqrtf(sx * sx + sy * sy);
            if (EDGE) {
                int gy = y0 - 2 + r, gx = x0 - 2 + c;
                if (!((unsigned)gy < IH && (unsigned)gx < IW)) { sx = 0.f; sy = 0.f; gm = 0.f; }
            }
            if (j < cnt) { s_sx[r][c] = sx; s_sy[r][c] = sy; s_gm[r][c] = gm; }
            u0 = u1; u1 = u2; v0 = v1; v1 = v2;
        }
    }
    #pragma unroll
    for (int p = 0; p < 2; p++) {                 // extra cols 32..35 (direct sobel)
        int idx = tid + 256 * p;
        if (idx < 272) {
            int r = idx >> 2, c = 32 + (idx & 3);
            float a00 = s_img[r][c],     a01 = s_img[r][c + 1],     a02 = s_img[r][c + 2];
            float a10 = s_img[r + 1][c],                            a12 = s_img[r + 1][c + 2];
            float a20 = s_img[r + 2][c], a21 = s_img[r + 2][c + 1], a22 = s_img[r + 2][c + 2];
            float sx = (0.5f * (a02 - a00) + (a12 - a10) + 0.5f * (a22 - a20)) * INV3;
            float sy = (0.5f * (a20 - a00) + (a21 - a01) + 0.5f * (a22 - a02)) * INV3;
            float gm = sqrtf(sx * sx + sy * sy);
            if (EDGE) {
                int gy = y0 - 2 + r, gx = x0 - 2 + c;
                if (!((unsigned)gy < IH && (unsigned)gx < IW)) { sx = 0.f; sy = 0.f; gm = 0.f; }
            }
            s_sx[r][c] = sx; s_sy[r][c] = sy; s_gm[r][c] = gm;
        }
    }
    __syncthreads();

    // ---- P3: orientation quantization + NMS -> t (rows 0..65, cols 0..33) ----
    float (*__restrict__ s_t)[36] = (float (*)[36])buf0;   // s_img dead now
    {
        int base = (66 * ty) >> 3;
        int cnt  = ((66 * (ty + 1)) >> 3) - base;
        int c = tx;
        #pragma unroll
        for (int j = 0; j < 9; j++) {
            int r = base + j;
            float sx = s_sx[r + 1][c + 1], sy = s_sy[r + 1][c + 1], gm = s_gm[r + 1][c + 1];
            float ax = fabsf(sx), ay = fabsf(sy);
            int mm = (int)(ay > T0 * ax) + (int)(ay > T1 * ax)
                   + (int)(ay > T2 * ax) + (int)(ay > T3 * ax);
            int neg = (__float_as_int(sx) ^ __float_as_int(sy)) < 0;
            int q = neg ? 4 - mm : 4 + mm;
            int k = q & 3;
            int dy = (k == 0) ? 0 : -1;
            int dx = 1 - (int)(k >= 2) - (int)(k == 3);
            float dp = gm - s_gm[r + 1 + dy][c + 1 + dx];
            float dn = gm - s_gm[r + 1 - dy][c + 1 - dx];
            float thin = (fminf(dp, dn) > 0.0f) ? gm : 0.0f;
            float t = (thin > 0.5f ? 0.5f : 0.0f) + (thin > 1.0f ? 0.5f : 0.0f);
            if (EDGE) {
                int gy = y0 - 1 + r, gx = x0 - 1 + c;
                if (!((unsigned)gy < IH && (unsigned)gx < IW)) t = 0.0f;
            }
            if (j < cnt) s_t[r][c] = t;
        }
    }
    {
        int idx = tid;                             // extra cols 32..33 (132 items)
        if (idx < 132) {
            int r = idx >> 1, c = 32 + (idx & 1);
            float sx = s_sx[r + 1][c + 1], sy = s_sy[r + 1][c + 1], gm = s_gm[r + 1][c + 1];
            float ax = fabsf(sx), ay = fabsf(sy);
            int mm = (int)(ay > T0 * ax) + (int)(ay > T1 * ax)
                   + (int)(ay > T2 * ax) + (int)(ay > T3 * ax);
            int neg = (__float_as_int(sx) ^ __float_as_int(sy)) < 0;
            int q = neg ? 4 - mm : 4 + mm;
            int k = q & 3;
            int dy = (k == 0) ? 0 : -1;
            int dx = 1 - (int)(k >= 2) - (int)(k == 3);
            float dp = gm - s_gm[r + 1 + dy][c + 1 + dx];
            float dn = gm - s_gm[r + 1 - dy][c + 1 - dx];
            float thin = (fminf(dp, dn) > 0.0f) ? gm : 0.0f;
            float t = (thin > 0.5f ? 0.5f : 0.0f) + (thin > 1.0f ? 0.5f : 0.0f);
            if (EDGE) {
                int gy = y0 - 1 + r, gx = x0 - 1 + c;
                if (!((unsigned)gy < IH && (unsigned)gx < IW)) t = 0.0f;
            }
            s_t[r][c] = t;
        }
    }
    __syncthreads();

    // ---- P4: hysteresis (rolling row-sums) + write 5 planes (64x32 center) ----
    const size_t plane = (size_t)NB * IH * IW;
    float* o_gx = out;
    float* o_gy = out + plane;
    float* o_gm = out + 2 * plane;
    float* o_or = out + 3 * plane;
    float* o_te = out + 4 * plane;
    {
        int r0 = 8 * ty, ix = tx;
        float rs0 = s_t[r0][ix]     + s_t[r0][ix + 1]     + s_t[r0][ix + 2];
        float rs1 = s_t[r0 + 1][ix] + s_t[r0 + 1][ix + 1] + s_t[r0 + 1][ix + 2];
        size_t obase = (size_t)b * IH * IW + (size_t)(y0 + r0) * IW + (x0 + ix);
        #pragma unroll
        for (int j = 0; j < 8; j++) {
            int iy = r0 + j;
            float rs2 = s_t[iy + 2][ix] + s_t[iy + 2][ix + 1] + s_t[iy + 2][ix + 2];
            float sum = rs0 + rs1 + rs2;
            float tc = s_t[iy + 1][ix + 1];
            float sx = s_sx[iy + 2][ix + 2];
            float sy = s_sy[iy + 2][ix + 2];
            float gm = s_gm[iy + 2][ix + 2];
            float ax = fabsf(sx), ay = fabsf(sy);
            int mm = (int)(ay > T0 * ax) + (int)(ay > T1 * ax)
                   + (int)(ay > T2 * ax) + (int)(ay > T3 * ax);
            int neg = (__float_as_int(sx) ^ __float_as_int(sy)) < 0;
            int q = neg ? 4 - mm : 4 + mm;
            float qv = (float)q * 45.0f;
            if (ax == 0.0f && ay == 0.0f) qv = __int_as_float(0x7fc00000);
            float high = (tc == 1.0f) ? 1.0f : 0.0f;
            float weak = ((sum * 1.25f > 1.0f) && (tc == 0.5f)) ? 1.0f : 0.0f;
            size_t o = obase + (size_t)j * IW;
            o_gx[o] = sx;
            o_gy[o] = sy;
            o_gm[o] = gm;
            o_or[o] = qv;
            o_te[o] = high + weak;
            rs0 = rs1; rs1 = rs2;
        }
    }
}

__global__ __launch_bounds__(256)
void canny_fused_kernel(const float* __restrict__ img, float* __restrict__ out)
{
    __shared__ float s_buf0[72 * 40];
    __shared__ float s_sx[68][40];
    __shared__ float s_sy[68][40];
    __shared__ float s_gm[68][40];

    const int b  = blockIdx.z;
    const int x0 = blockIdx.x * TW;
    const int y0 = blockIdx.y * TH;
    const int tx = threadIdx.x;
    const int ty = threadIdx.y;
    const int tid = ty * 32 + tx;

    const float* imgb = img + (size_t)b * 3 * IH * IW;

    const bool edge = (x0 == 0) || (y0 == 0) || (x0 + TW == IW) || (y0 + TH == IH);
    if (edge)
        body<true >(imgb, out, b, x0, y0, tx, ty, tid, s_buf0, s_sx, s_sy, s_gm);
    else
        body<false>(imgb, out, b, x0, y0, tx, ty, tid, s_buf0, s_sx, s_sy, s_gm);
}

extern "C" void kernel_launch(void* const* d_in, const int* in_sizes, int n_in,
                              void* d_out, int out_size)
{
    const float* img = (const float*)d_in[0];
    float* out = (float*)d_out;
    dim3 block(32, 8, 1);
    dim3 grid(IW / TW, IH / TH, NB);
    canny_fused_kernel<<<grid, block>>>(img, out);
}

// round 4
// speedup vs baseline: 1.3786x; 1.0008x over previous
#include <cuda_runtime.h>
#include <cuda_bf16.h>
#include <math.h>

#define IH 1024
#define IW 1024
#define NB 8
#define TW 32
#define TH 64
#define SIW 40   // s_img row stride (floats)
#define SW  36   // s_sx/s_sy/s_gm/s_t row stride

// tan((2k+1)*pi/16)
#define T0 0.1989123673796580f
#define T1 0.6681786379192989f
#define T2 1.4966057626654890f
#define T3 5.0273394921258481f
#define INV3 0.3333333333333333f

template<bool EDGE>
__device__ __forceinline__ void body(
    const float* __restrict__ imgb, float* __restrict__ out,
    int b, int x0, int y0, int tx, int ty, int tid,
    float* __restrict__ s_img,   // 70*40 floats; reused as s_t (66*36) after P2
    float* __restrict__ s_sx, float* __restrict__ s_sy, float* __restrict__ s_gm)
{
    // ---- P1: channel-summed image. smem col c <-> gx = x0-4+c (c=0..39), row r <-> gy = y0-3+r (r=0..69)
    if (!EDGE) {
        const float4* base = (const float4*)(imgb + (size_t)(y0 - 3) * IW + (x0 - 4));
        const int CH4 = IH * IW / 4;
        #pragma unroll
        for (int p = 0; p < 3; p++) {
            int idx = tid + 256 * p;
            if (idx < 700) {
                int r = idx / 10, c4 = idx % 10;
                const float4* ptr = base + r * (IW / 4) + c4;
                float4 v0 = ptr[0], v1 = ptr[CH4], v2 = ptr[2 * CH4];
                float4 s;
                s.x = v0.x + v1.x + v2.x; s.y = v0.y + v1.y + v2.y;
                s.z = v0.z + v1.z + v2.z; s.w = v0.w + v1.w + v2.w;
                *(float4*)&s_img[r * SIW + c4 * 4] = s;
            }
        }
    } else {
        #pragma unroll
        for (int p = 0; p < 11; p++) {
            int idx = tid + 256 * p;
            if (idx < 2800) {
                int r = idx / 40, c = idx % 40;
                int gy = y0 - 3 + r, gx = x0 - 4 + c;
                float v = 0.0f;
                if ((unsigned)gy < IH && (unsigned)gx < IW) {
                    size_t o = (size_t)gy * IW + gx;
                    v = imgb[o] + imgb[o + IH * IW] + imgb[o + 2 * IH * IW];
                }
                s_img[r * SIW + c] = v;
            }
        }
    }
    __syncthreads();

    // ---- P2: sobel. gm row r <-> gy = y0-2+r (r=0..67), col c <-> gx = x0-2+c (c=0..35).
    // taps: s_img rows r..r+2, cols c+1..c+3. Canonical separable composition everywhere.
    auto p2_at = [&](int r, int c) {
        const float* ip = s_img + r * SIW + (c + 1);
        float a0 = ip[0],         a1 = ip[1],         a2 = ip[2];
        float b0 = ip[SIW],       b1 = ip[SIW + 1],   b2 = ip[SIW + 2];
        float c0 = ip[2 * SIW],   c1 = ip[2 * SIW + 1], c2 = ip[2 * SIW + 2];
        float u0 = a2 - a0, v0 = 0.5f * (a0 + a2) + a1;
        float u1 = b2 - b0;
        float u2 = c2 - c0, v2 = 0.5f * (c0 + c2) + c1;
        float sx = (0.5f * (u0 + u2) + u1) * INV3;
        float sy = (v2 - v0) * INV3;
        float gm = sqrtf(sx * sx + sy * sy);
        if (EDGE) {
            int gy = y0 - 2 + r, gx = x0 - 2 + c;
            if (!((unsigned)gy < IH && (unsigned)gx < IW)) { sx = 0.f; sy = 0.f; gm = 0.f; }
        }
        s_sx[r * SW + c] = sx; s_sy[r * SW + c] = sy; s_gm[r * SW + c] = gm;
    };
    {   // main rolling: rows 2..65, cols 0..31 (8 rows/thread, even)
        int r0 = 2 + 8 * ty, c = tx;
        const float* ip = s_img + r0 * SIW + (c + 1);
        float a0 = ip[0], a1 = ip[1], a2 = ip[2];
        float u0 = a2 - a0, v0 = 0.5f * (a0 + a2) + a1;
        float b0 = ip[SIW], b1 = ip[SIW + 1], b2 = ip[SIW + 2];
        float u1 = b2 - b0, v1 = 0.5f * (b0 + b2) + b1;
        #pragma unroll
        for (int j = 0; j < 8; j++) {
            const float* rp = ip + (j + 2) * SIW;
            float c0 = rp[0], c1 = rp[1], c2 = rp[2];
            float u2 = c2 - c0, v2 = 0.5f * (c0 + c2) + c1;
            float sx = (0.5f * (u0 + u2) + u1) * INV3;
            float sy = (v2 - v0) * INV3;
            float gm = sqrtf(sx * sx + sy * sy);
            int r = r0 + j;
            if (EDGE) {
                int gy = y0 - 2 + r, gx = x0 - 2 + c;
                if (!((unsigned)gy < IH && (unsigned)gx < IW)) { sx = 0.f; sy = 0.f; gm = 0.f; }
            }
            s_sx[r * SW + c] = sx; s_sy[r * SW + c] = sy; s_gm[r * SW + c] = gm;
            u0 = u1; u1 = u2; v0 = v1; v1 = v2;
        }
    }
    if (tid < 144) {           // tail A: rows {0,1,66,67} x cols 0..35
        int rr = tid / 36, c = tid % 36;
        int r = (rr < 2) ? rr : 64 + rr;
        p2_at(r, c);
    }
    {                           // tail B: rows 2..65 x cols 32..35 (exactly 256)
        int r = 2 + (tid >> 2), c = 32 + (tid & 3);
        p2_at(r, c);
    }
    __syncthreads();

    // ---- P3: orientation quant + NMS -> t. t row r <-> gy = y0-1+r (r=0..65), col c <-> gx = x0-1+c (c=0..33)
    float* s_t = s_img;   // s_img dead now
    auto p3_at = [&](int r, int c) {
        float sx = s_sx[(r + 1) * SW + c + 1];
        float sy = s_sy[(r + 1) * SW + c + 1];
        float gm = s_gm[(r + 1) * SW + c + 1];
        float ax = fabsf(sx), ay = fabsf(sy);
        int mm = (int)(ay > T0 * ax) + (int)(ay > T1 * ax)
               + (int)(ay > T2 * ax) + (int)(ay > T3 * ax);
        int neg = (__float_as_int(sx) ^ __float_as_int(sy)) < 0;
        int q = neg ? 4 - mm : 4 + mm;
        int k = q & 3;
        int dy = (k == 0) ? 0 : -1;                    // offs (0,1)(-1,1)(-1,0)(-1,-1)
        int dx = 1 - (int)(k >= 2) - (int)(k == 3);
        float dp = gm - s_gm[(r + 1 + dy) * SW + c + 1 + dx];
        float dn = gm - s_gm[(r + 1 - dy) * SW + c + 1 - dx];
        float thin = (fminf(dp, dn) > 0.0f) ? gm : 0.0f;
        float t = (thin > 0.5f ? 0.5f : 0.0f) + (thin > 1.0f ? 0.5f : 0.0f);
        if (EDGE) {
            int gy = y0 - 1 + r, gx = x0 - 1 + c;
            if (!((unsigned)gy < IH && (unsigned)gx < IW)) t = 0.0f;
        }
        s_t[r * SW + c] = t;
    };
    {   // main: rows 1..64, cols 0..31
        int r0 = 1 + 8 * ty, c = tx;
        #pragma unroll
        for (int j = 0; j < 8; j++) p3_at(r0 + j, c);
    }
    if (tid < 68) {            // tail A: rows {0,65} x cols 0..33
        int rr = tid / 34, c = tid % 34;
        p3_at(rr ? 65 : 0, c);
    } else if (tid < 196) {    // tail B: rows 1..64 x cols 32..33
        int k2 = tid - 68;
        p3_at(1 + (k2 >> 1), 32 + (k2 & 1));
    }
    __syncthreads();

    // ---- P4: hysteresis (rolling 3-tap row sums) + write 5 planes ----
    const size_t plane = (size_t)NB * IH * IW;
    float* o_gx = out;
    float* o_gy = out + plane;
    float* o_gm = out + 2 * plane;
    float* o_or = out + 3 * plane;
    float* o_te = out + 4 * plane;
    {
        int r0 = 8 * ty, ix = tx;
        const float* tp = s_t + r0 * SW + ix;
        float rs0 = tp[0]  + tp[1]      + tp[2];
        float rs1 = tp[SW] + tp[SW + 1] + tp[SW + 2];
        size_t obase = (size_t)b * IH * IW + (size_t)(y0 + r0) * IW + (x0 + ix);
        #pragma unroll
        for (int j = 0; j < 8; j++) {
            const float* rp = tp + (j + 2) * SW;
            float rs2 = rp[0] + rp[1] + rp[2];
            float sum = rs0 + rs1 + rs2;
            float tc = tp[(j + 1) * SW + 1];
            int iy = r0 + j;
            float sx = s_sx[(iy + 2) * SW + ix + 2];
            float sy = s_sy[(iy + 2) * SW + ix + 2];
            float gm = s_gm[(iy + 2) * SW + ix + 2];
            float ax = fabsf(sx), ay = fabsf(sy);
            int mm = (int)(ay > T0 * ax) + (int)(ay > T1 * ax)
                   + (int)(ay > T2 * ax) + (int)(ay > T3 * ax);
            int neg = (__float_as_int(sx) ^ __float_as_int(sy)) < 0;
            int q = neg ? 4 - mm : 4 + mm;
            float qv = (float)q * 45.0f;
            if (ax == 0.0f && ay == 0.0f) qv = __int_as_float(0x7fc00000);
            float high = (tc == 1.0f) ? 1.0f : 0.0f;
            float weak = ((sum * 1.25f > 1.0f) && (tc == 0.5f)) ? 1.0f : 0.0f;
            size_t o = obase + (size_t)j * IW;
            __stcs(o_gx + o, sx);
            __stcs(o_gy + o, sy);
            __stcs(o_gm + o, gm);
            __stcs(o_or + o, qv);
            __stcs(o_te + o, high + weak);
            rs0 = rs1; rs1 = rs2;
        }
    }
}

__global__ __launch_bounds__(256)
void canny_fused_kernel(const float* __restrict__ img, float* __restrict__ out)
{
    __shared__ float s_buf0[70 * SIW];     // s_img / s_t
    __shared__ float s_sx[68 * SW];
    __shared__ float s_sy[68 * SW];
    __shared__ float s_gm[68 * SW];

    const int b  = blockIdx.z;
    const int x0 = blockIdx.x * TW;
    const int y0 = blockIdx.y * TH;
    const int tx = threadIdx.x;
    const int ty = threadIdx.y;
    const int tid = ty * 32 + tx;

    const float* imgb = img + (size_t)b * 3 * IH * IW;

    const bool edge = (x0 == 0) || (y0 == 0) || (x0 + TW == IW) || (y0 + TH == IH);
    if (edge)
        body<true >(imgb, out, b, x0, y0, tx, ty, tid, s_buf0, s_sx, s_sy, s_gm);
    else
        body<false>(imgb, out, b, x0, y0, tx, ty, tid, s_buf0, s_sx, s_sy, s_gm);
}

extern "C" void kernel_launch(void* const* d_in, const int* in_sizes, int n_in,
                              void* d_out, int out_size)
{
    const float* img = (const float*)d_in[0];
    float* out = (float*)d_out;
    dim3 block(32, 8, 1);
    dim3 grid(IW / TW, IH / TH, NB);
    canny_fused_kernel<<<grid, block>>>(img, out);
}